// round 16
// baseline (speedup 1.0000x reference)
#include <cuda_runtime.h>
#include <cuda_fp16.h>
#include <cstdint>
#include <cstddef>

// Problem constants
#define BB 4
#define SS 2048
#define DD 1024
#define HH 16
#define DK 64
#define MM (BB * SS)   // 8192

// fp16 operands
__device__ __half g_q16[(size_t)MM * DD];        // q * 0.125 (softmax scale folded)
__device__ __half g_k16[(size_t)MM * DD];
__device__ __half g_v16[(size_t)MM * DD];
__device__ __half g_Wq16[DD * DD];
__device__ __half g_Wk16[DD * DD];
__device__ __half g_Wv16[DD * DD];
__device__ __half g_Wo16[DD * DD];
__device__ __half g_Q16[(size_t)MM * DD];        // [B,H,S,DK]
__device__ __half g_K16[(size_t)MM * DD];        // [B,H,S,DK]
__device__ __half g_Vt16[(size_t)MM * DD];       // [B,H,DK,S]
__device__ __half g_O16[(size_t)MM * DD];        // [B,H,S,DK]

// ---------------------------------------------------------------------------
// Helpers
// ---------------------------------------------------------------------------
__device__ __forceinline__ uint32_t smem_u32(const void* p) {
    uint32_t a;
    asm("{ .reg .u64 t; cvta.to.shared.u64 t, %1; cvt.u32.u64 %0, t; }"
        : "=r"(a) : "l"(p));
    return a;
}
__device__ __forceinline__ void cp16(uint32_t saddr, const void* gptr) {
    asm volatile("cp.async.ca.shared.global [%0], [%1], 16;"
                 :: "r"(saddr), "l"(gptr) : "memory");
}
__device__ __forceinline__ void cp_commit() {
    asm volatile("cp.async.commit_group;" ::: "memory");
}
template <int N>
__device__ __forceinline__ void cp_wait() {
    asm volatile("cp.async.wait_group %0;" :: "n"(N) : "memory");
}
// pack two fp32 -> f16x2 register (lo = first k element)
__device__ __forceinline__ uint32_t pack_h2(float lo, float hi) {
    uint32_t u;
    asm("cvt.rn.f16x2.f32 %0, %1, %2;" : "=r"(u) : "f"(hi), "f"(lo));
    return u;
}
__device__ __forceinline__ void mma_f16(float* d, const uint32_t* a, const uint32_t* b) {
    asm volatile(
        "mma.sync.aligned.m16n8k16.row.col.f32.f16.f16.f32 "
        "{%0,%1,%2,%3}, {%4,%5,%6,%7}, {%8,%9}, {%0,%1,%2,%3};"
        : "+f"(d[0]), "+f"(d[1]), "+f"(d[2]), "+f"(d[3])
        : "r"(a[0]), "r"(a[1]), "r"(a[2]), "r"(a[3]), "r"(b[0]), "r"(b[1]));
}
__device__ __forceinline__ void ldsm4(uint32_t* r, uint32_t addr) {
    asm volatile("ldmatrix.sync.aligned.m8n8.x4.shared.b16 {%0,%1,%2,%3}, [%4];"
                 : "=r"(r[0]), "=r"(r[1]), "=r"(r[2]), "=r"(r[3]) : "r"(addr));
}

// ---------------------------------------------------------------------------
// Pre-pass: fp16 conversion of all 7 inputs. grid (8192, 7). q scaled 0.125.
// ---------------------------------------------------------------------------
#define NBIG4 ((int)((size_t)MM * DD / 4))   // 2097152
#define NW4 (DD * DD / 4)                    // 262144

__global__ __launch_bounds__(256)
void cvt_all(const float4* __restrict__ q, const float4* __restrict__ k,
             const float4* __restrict__ v, const float4* __restrict__ Wq,
             const float4* __restrict__ Wk, const float4* __restrict__ Wv,
             const float4* __restrict__ Wo)
{
    const int y = blockIdx.y;
    const int i = blockIdx.x * blockDim.x + threadIdx.x;
    const float4* src;
    __half* dst;
    int n4;
    float scale = 1.0f;
    switch (y) {
        case 0: src = q;  dst = g_q16;  n4 = NBIG4; scale = 0.125f; break;
        case 1: src = k;  dst = g_k16;  n4 = NBIG4; break;
        case 2: src = v;  dst = g_v16;  n4 = NBIG4; break;
        case 3: src = Wq; dst = g_Wq16; n4 = NW4; break;
        case 4: src = Wk; dst = g_Wk16; n4 = NW4; break;
        case 5: src = Wv; dst = g_Wv16; n4 = NW4; break;
        default: src = Wo; dst = g_Wo16; n4 = NW4; break;
    }
    if (i < n4) {
        float4 x = src[i];
        x.x *= scale; x.y *= scale; x.z *= scale; x.w *= scale;
        __half2 h0 = __floats2half2_rn(x.x, x.y);
        __half2 h1 = __floats2half2_rn(x.z, x.w);
        *(__half2*)&dst[(size_t)i * 4]     = h0;
        *(__half2*)&dst[(size_t)i * 4 + 2] = h1;
    }
}

// ---------------------------------------------------------------------------
// fp16 GEMM core: C = A @ W^T, tile 128x128, BK=64, 128 threads, 4 warps 64x64.
// 2-stage cp.async pipeline. (R14 exact — best measured.)
// ---------------------------------------------------------------------------
#define RH 72                          // halves per smem row (64 + pad 8)
#define TILEB (128 * RH * 2)           // 18432 bytes per tile
#define BUFB (2 * TILEB)               // A + B = 36864
#define GSMEM (2 * BUFB)               // 73728
#define NCHUNK (DD / 64)               // 16

template <bool GATHER>
__device__ __forceinline__ void issue_chunk(uint32_t sbuf, int it,
                                            const __half* __restrict__ A,
                                            const __half* __restrict__ W,
                                            int bm, int bn, int tid)
{
    const int k0 = it * 64;
    #pragma unroll
    for (int i = 0; i < 8; i++) {
        const int idx = i * 128 + tid;       // 0..1023 (8-half slots)
        const int r = idx >> 3;              // 0..127
        const int c8 = idx & 7;
        const int gk = k0 + c8 * 8;
        size_t aoff;
        if (GATHER) {
            const int gm = bm + r;
            const int b = gm >> 11;
            const int s = gm & (SS - 1);
            const int h = gk >> 6;
            const int dk = gk & (DK - 1);
            aoff = ((((size_t)b * HH + h) * SS + s) << 6) + dk;
        } else {
            aoff = (size_t)(bm + r) * DD + gk;
        }
        const uint32_t soff = (uint32_t)(r * RH + c8 * 8) * 2u;
        cp16(sbuf + soff, &A[aoff]);
        cp16(sbuf + TILEB + soff, &W[(size_t)(bn + r) * DD + gk]);
    }
    cp_commit();
}

template <bool GATHER>
__device__ __forceinline__ void gemm_core(const __half* __restrict__ A,
                                          const __half* __restrict__ W,
                                          float (&acc)[4][8][4],
                                          int bm, int bn, char* smem)
{
    const uint32_t sb = smem_u32(smem);
    const int tid = threadIdx.x;
    const int lane = tid & 31;
    const int wid = tid >> 5;       // 0..3
    const int wm = wid >> 1;        // 0..1 (64-row slab)
    const int wn = wid & 1;         // 0..1 (64-col slab)
    const uint32_t lrow = (uint32_t)(lane & 15);
    const uint32_t lcol = (uint32_t)(lane >> 4) * 8u;

    const uint32_t aoff = ((wm * 64 + lrow) * RH + lcol) * 2u;
    const uint32_t boff = ((wn * 64 + lrow) * RH + lcol) * 2u;

    const uint32_t sbuf[2] = { sb, sb + (uint32_t)BUFB };

    issue_chunk<GATHER>(sbuf[0], 0, A, W, bm, bn, tid);

    for (int it = 0; it < NCHUNK; ++it) {
        const int cur = it & 1;
        if (it + 1 < NCHUNK) {
            issue_chunk<GATHER>(sbuf[cur ^ 1], it + 1, A, W, bm, bn, tid);
            cp_wait<1>();
        } else {
            cp_wait<0>();
        }
        __syncthreads();

        const uint32_t aT = sbuf[cur] + aoff;
        const uint32_t bT = sbuf[cur] + TILEB + boff;
        #pragma unroll
        for (int ks = 0; ks < 4; ks++) {        // 4 k16 steps per 64-chunk
            const uint32_t koff = (uint32_t)ks * 32u;   // 16 halves
            uint32_t afr[4][4], bfr[8][2];
            #pragma unroll
            for (int mt = 0; mt < 4; mt++)
                ldsm4(afr[mt], aT + (uint32_t)(mt * 16 * RH) * 2u + koff);
            #pragma unroll
            for (int p = 0; p < 4; p++) {
                uint32_t r4[4];
                ldsm4(r4, bT + (uint32_t)(p * 16 * RH) * 2u + koff);
                bfr[2 * p][0] = r4[0]; bfr[2 * p][1] = r4[2];
                bfr[2 * p + 1][0] = r4[1]; bfr[2 * p + 1][1] = r4[3];
            }
            #pragma unroll
            for (int mt = 0; mt < 4; mt++)
                #pragma unroll
                for (int nt = 0; nt < 8; nt++)
                    mma_f16(acc[mt][nt], afr[mt], bfr[nt]);
        }
        __syncthreads();
    }
}

// Fused Q/K/V projections: grid (8, 64, 3). z=0 -> Q16, z=1 -> K16, z=2 -> Vt16.
__global__ __launch_bounds__(128, 2)
void gemm_qkv()
{
    extern __shared__ char smem[];
    const int z = blockIdx.z;
    const __half *A, *W;
    __half* C;
    if (z == 0) { A = g_q16; W = g_Wq16; C = g_Q16; }
    else if (z == 1) { A = g_k16; W = g_Wk16; C = g_K16; }
    else { A = g_v16; W = g_Wv16; C = g_Vt16; }
    const int bm = blockIdx.y * 128;
    const int bn = blockIdx.x * 128;

    float acc[4][8][4];
    #pragma unroll
    for (int i = 0; i < 4; i++)
        #pragma unroll
        for (int j = 0; j < 8; j++)
            #pragma unroll
            for (int r = 0; r < 4; r++) acc[i][j][r] = 0.f;

    gemm_core<false>(A, W, acc, bm, bn, smem);

    const int lane = threadIdx.x & 31;
    const int wid = threadIdx.x >> 5;
    const int g = lane >> 2;
    const int tig = lane & 3;
    const int wm = wid >> 1;
    const int wn = wid & 1;

    #pragma unroll
    for (int mt = 0; mt < 4; mt++) {
        #pragma unroll
        for (int half = 0; half < 2; half++) {
            const int gm = bm + wm * 64 + mt * 16 + g + half * 8;
            const int b = gm >> 11;
            const int s = gm & (SS - 1);
            #pragma unroll
            for (int nt = 0; nt < 8; nt++) {
                const int gn = bn + wn * 64 + nt * 8 + 2 * tig;
                const float vx = acc[mt][nt][half * 2 + 0];
                const float vy = acc[mt][nt][half * 2 + 1];
                const int h = gn >> 6;
                const int dk = gn & (DK - 1);
                if (z < 2) {
                    *(__half2*)&C[((((size_t)b * HH + h) * SS + s) << 6) + dk] =
                        __floats2half2_rn(vx, vy);
                } else {
                    const size_t base = (((size_t)b * HH + h) * DK);
                    C[(base + dk) * SS + s] = __float2half_rn(vx);
                    C[(base + dk + 1) * SS + s] = __float2half_rn(vy);
                }
            }
        }
    }
}

// Output projection: gather-A from head-split O16, fp32 epilogue to out.
__global__ __launch_bounds__(128, 2)
void gemm_o(float* __restrict__ C)
{
    extern __shared__ char smem[];
    const int bm = blockIdx.y * 128;
    const int bn = blockIdx.x * 128;

    float acc[4][8][4];
    #pragma unroll
    for (int i = 0; i < 4; i++)
        #pragma unroll
        for (int j = 0; j < 8; j++)
            #pragma unroll
            for (int r = 0; r < 4; r++) acc[i][j][r] = 0.f;

    gemm_core<true>(g_O16, g_Wo16, acc, bm, bn, smem);

    const int lane = threadIdx.x & 31;
    const int wid = threadIdx.x >> 5;
    const int g = lane >> 2;
    const int tig = lane & 3;
    const int wm = wid >> 1;
    const int wn = wid & 1;

    #pragma unroll
    for (int mt = 0; mt < 4; mt++) {
        #pragma unroll
        for (int half = 0; half < 2; half++) {
            const int gm = bm + wm * 64 + mt * 16 + g + half * 8;
            #pragma unroll
            for (int nt = 0; nt < 8; nt++) {
                const int gn = bn + wn * 64 + nt * 8 + 2 * tig;
                float2 o;
                o.x = acc[mt][nt][half * 2 + 0];
                o.y = acc[mt][nt][half * 2 + 1];
                *(float2*)&C[(size_t)gm * DD + gn] = o;
            }
        }
    }
}

// ---------------------------------------------------------------------------
// fp16 causal flash attention, 128 threads (4 warps x 32 queries), QT=128.
// K/V staged in 128-key blocks; two 64-key compute halves per staged block
// (same rescale points / accumulation order as R14 -> bit-identical output).
// Q16/K16 [B,H,S,DK]; Vt16 [B,H,DK,S]. m16n8k16; no shfl transpose.
// ---------------------------------------------------------------------------
#define QT 128
#define ASTK 72                         // K tile row stride (64 dk + pad)
#define ASTV 136                        // V tile row stride (128 keys + pad)
#define KTB (128 * ASTK * 2)            // 18432 bytes (also Q tile size)
#define VTB (64 * ASTV * 2)             // 17408 bytes
#define ASMEM (2 * (KTB + VTB))         // 71680 bytes

__device__ __forceinline__ void attn_stage(uint32_t sK, uint32_t sV,
                                           const __half* __restrict__ Kh,
                                           const __half* __restrict__ Vt,
                                           size_t headoff, int kb, int tid)
{
    // K: 128 key rows x 64 dk
    #pragma unroll
    for (int i = 0; i < 8; i++) {
        const int idx = i * 128 + tid;       // 0..1023 (8-half slots)
        const int r = idx >> 3;              // 0..127
        const int c8 = idx & 7;
        cp16(sK + (uint32_t)(r * ASTK + c8 * 8) * 2u,
             &Kh[headoff + (size_t)(kb * 128 + r) * DK + c8 * 8]);
    }
    // V: 64 dk rows x 128 keys
    #pragma unroll
    for (int i = 0; i < 8; i++) {
        const int idx = i * 128 + tid;       // 0..1023
        const int r = idx >> 4;              // 0..63
        const int c16 = idx & 15;
        cp16(sV + (uint32_t)(r * ASTV + c16 * 8) * 2u,
             &Vt[headoff + (size_t)r * SS + kb * 128 + c16 * 8]);
    }
    cp_commit();
}

__global__ __launch_bounds__(128, 2)
void attn_mma(const __half* __restrict__ Qh, const __half* __restrict__ Kh,
              const __half* __restrict__ Vt)
{
    extern __shared__ char smc[];
    const uint32_t sb = smem_u32(smc);
    const uint32_t sK[2] = { sb, sb + (uint32_t)KTB };
    const uint32_t sV[2] = { sb + 2u * KTB, sb + 2u * KTB + (uint32_t)VTB };

    const int tid = threadIdx.x;
    const int wid = tid >> 5;
    const int lane = tid & 31;
    const int g = lane >> 2;
    const int tig = lane & 3;
    const uint32_t lrow = (uint32_t)(lane & 15);
    const uint32_t lcol = (uint32_t)(lane >> 4) * 8u;
    const int qt = gridDim.x - 1 - blockIdx.x;   // heavy tiles first
    const int h = blockIdx.y;
    const int b = blockIdx.z;
    const size_t headoff = ((size_t)(b * HH + h)) * SS * DK;
    const int nkb = qt + 1;                      // 128-key blocks

    // Stage Q (128 rows x 64) into sK[1] AND kb=0 K/V — single cp group.
    #pragma unroll
    for (int i = 0; i < 8; i++) {
        const int idx = i * 128 + tid;
        const int r = idx >> 3;
        const int c8 = idx & 7;
        cp16(sK[1] + (uint32_t)(r * ASTK + c8 * 8) * 2u,
             &Qh[headoff + (size_t)(qt * QT + r) * DK + c8 * 8]);
    }
    attn_stage(sK[0], sV[0], Kh, Vt, headoff, 0, tid);   // commits the group
    cp_wait<0>();
    __syncthreads();

    // Q fragments for both 16-row groups of this warp's 32 queries.
    uint32_t qf[2][4][4];
    #pragma unroll
    for (int grp = 0; grp < 2; grp++) {
        const uint32_t qbase = sK[1]
            + ((wid * 32 + grp * 16 + lrow) * ASTK + lcol) * 2u;
        #pragma unroll
        for (int ks = 0; ks < 4; ks++)
            ldsm4(qf[grp][ks], qbase + (uint32_t)ks * 32u);
    }
    __syncthreads();   // qf reads done before sK[1] is restaged (kb=1)

    const uint32_t foffK = (lrow * ASTK + lcol) * 2u;
    const uint32_t foffV = (lrow * ASTV + lcol) * 2u;

    float oacc[2][8][4];
    #pragma unroll
    for (int grp = 0; grp < 2; grp++)
        #pragma unroll
        for (int nt = 0; nt < 8; nt++)
            #pragma unroll
            for (int r = 0; r < 4; r++) oacc[grp][nt][r] = 0.f;
    float m[2][2] = { {-1e30f, -1e30f}, {-1e30f, -1e30f} };
    float l[2][2] = { {0.f, 0.f}, {0.f, 0.f} };

    for (int kb = 0; kb < nkb; kb++) {
        const int cur = kb & 1;
        if (kb + 1 < nkb) {
            attn_stage(sK[cur ^ 1], sV[cur ^ 1], Kh, Vt, headoff, kb + 1, tid);
            cp_wait<1>();
        } else {
            cp_wait<0>();
        }
        __syncthreads();

        #pragma unroll
        for (int hk = 0; hk < 2; hk++) {      // two 64-key halves per block
            // ---- S = Q K^T ----
            float sacc[2][8][4];
            #pragma unroll
            for (int grp = 0; grp < 2; grp++)
                #pragma unroll
                for (int nt = 0; nt < 8; nt++)
                    #pragma unroll
                    for (int r = 0; r < 4; r++) sacc[grp][nt][r] = 0.f;

            const uint32_t kT = sK[cur] + (uint32_t)(hk * 64 * ASTK) * 2u + foffK;
            #pragma unroll
            for (int ks = 0; ks < 4; ks++) {
                uint32_t bfr[8][2];
                #pragma unroll
                for (int p = 0; p < 4; p++) {
                    uint32_t r4[4];
                    ldsm4(r4, kT + (uint32_t)(p * 16 * ASTK) * 2u + (uint32_t)ks * 32u);
                    bfr[2 * p][0] = r4[0]; bfr[2 * p][1] = r4[2];
                    bfr[2 * p + 1][0] = r4[1]; bfr[2 * p + 1][1] = r4[3];
                }
                #pragma unroll
                for (int grp = 0; grp < 2; grp++)
                    #pragma unroll
                    for (int nt = 0; nt < 8; nt++)
                        mma_f16(sacc[grp][nt], qf[grp][ks], bfr[nt]);
            }

            // ---- causal mask (last two 64-key sub-blocks only) ----
            const int rel = (kb * 2 + hk - 2 * qt) * 64;
            if (rel >= 0) {
                #pragma unroll
                for (int grp = 0; grp < 2; grp++) {
                    const int ql0 = wid * 32 + grp * 16 + g;
                    const int ql1 = ql0 + 8;
                    #pragma unroll
                    for (int nt = 0; nt < 8; nt++) {
                        const int kc = rel + nt * 8 + 2 * tig;
                        if (kc > ql0)     sacc[grp][nt][0] = -1e30f;
                        if (kc + 1 > ql0) sacc[grp][nt][1] = -1e30f;
                        if (kc > ql1)     sacc[grp][nt][2] = -1e30f;
                        if (kc + 1 > ql1) sacc[grp][nt][3] = -1e30f;
                    }
                }
            }

            // ---- online softmax bookkeeping per group ----
            float nm[2][2];
            #pragma unroll
            for (int grp = 0; grp < 2; grp++) {
                float tmax0 = -1e30f, tmax1 = -1e30f;
                #pragma unroll
                for (int nt = 0; nt < 8; nt++) {
                    tmax0 = fmaxf(tmax0, fmaxf(sacc[grp][nt][0], sacc[grp][nt][1]));
                    tmax1 = fmaxf(tmax1, fmaxf(sacc[grp][nt][2], sacc[grp][nt][3]));
                }
                tmax0 = fmaxf(tmax0, __shfl_xor_sync(0xffffffffu, tmax0, 1));
                tmax0 = fmaxf(tmax0, __shfl_xor_sync(0xffffffffu, tmax0, 2));
                tmax1 = fmaxf(tmax1, __shfl_xor_sync(0xffffffffu, tmax1, 1));
                tmax1 = fmaxf(tmax1, __shfl_xor_sync(0xffffffffu, tmax1, 2));
                const float nm0 = fmaxf(m[grp][0], tmax0);
                const float nm1 = fmaxf(m[grp][1], tmax1);
                const float corr0 = __expf(m[grp][0] - nm0);
                const float corr1 = __expf(m[grp][1] - nm1);
                l[grp][0] *= corr0;
                l[grp][1] *= corr1;
                #pragma unroll
                for (int nt = 0; nt < 8; nt++) {
                    oacc[grp][nt][0] *= corr0; oacc[grp][nt][1] *= corr0;
                    oacc[grp][nt][2] *= corr1; oacc[grp][nt][3] *= corr1;
                }
                m[grp][0] = nm0; m[grp][1] = nm1;
                nm[grp][0] = nm0; nm[grp][1] = nm1;
            }

            // ---- PV: exp in C layout == A layout, pack f16x2, mma. ----
            const uint32_t vT = sV[cur] + (uint32_t)(hk * 64) * 2u + foffV;
            #pragma unroll
            for (int ks2 = 0; ks2 < 4; ks2++) {     // 16 keys per step
                uint32_t bfr[8][2];
                #pragma unroll
                for (int p = 0; p < 4; p++) {
                    uint32_t r4[4];
                    ldsm4(r4, vT + (uint32_t)(p * 16 * ASTV) * 2u + (uint32_t)ks2 * 32u);
                    bfr[2 * p][0] = r4[0]; bfr[2 * p][1] = r4[2];
                    bfr[2 * p + 1][0] = r4[1]; bfr[2 * p + 1][1] = r4[3];
                }
                #pragma unroll
                for (int grp = 0; grp < 2; grp++) {
                    const int nt0 = 2 * ks2, nt1 = 2 * ks2 + 1;
                    const float p00 = __expf(sacc[grp][nt0][0] - nm[grp][0]);
                    const float p01 = __expf(sacc[grp][nt0][1] - nm[grp][0]);
                    const float p02 = __expf(sacc[grp][nt0][2] - nm[grp][1]);
                    const float p03 = __expf(sacc[grp][nt0][3] - nm[grp][1]);
                    const float p10 = __expf(sacc[grp][nt1][0] - nm[grp][0]);
                    const float p11 = __expf(sacc[grp][nt1][1] - nm[grp][0]);
                    const float p12 = __expf(sacc[grp][nt1][2] - nm[grp][1]);
                    const float p13 = __expf(sacc[grp][nt1][3] - nm[grp][1]);
                    l[grp][0] += (p00 + p01) + (p10 + p11);
                    l[grp][1] += (p02 + p03) + (p12 + p13);
                    uint32_t af[4];
                    af[0] = pack_h2(p00, p01);
                    af[1] = pack_h2(p02, p03);
                    af[2] = pack_h2(p10, p11);
                    af[3] = pack_h2(p12, p13);
                    #pragma unroll
                    for (int nt = 0; nt < 8; nt++)
                        mma_f16(oacc[grp][nt], af, bfr[nt]);
                }
            }
        }
        __syncthreads();   // all reads of buf[cur] done before it is restaged
    }

    // Epilogue: O as fp16 head-split (consumed by gemm_o).
    #pragma unroll
    for (int grp = 0; grp < 2; grp++) {
        float la = l[grp][0], lb = l[grp][1];
        la += __shfl_xor_sync(0xffffffffu, la, 1);
        la += __shfl_xor_sync(0xffffffffu, la, 2);
        lb += __shfl_xor_sync(0xffffffffu, lb, 1);
        lb += __shfl_xor_sync(0xffffffffu, lb, 2);
        const float inv0 = 1.f / la;
        const float inv1 = 1.f / lb;
        const int qr0 = qt * QT + wid * 32 + grp * 16 + g;
        const int qr1 = qr0 + 8;
        #pragma unroll
        for (int nt = 0; nt < 8; nt++) {
            const int d = nt * 8 + 2 * tig;
            const size_t off0 = headoff + (size_t)qr0 * DK + d;
            const size_t off1 = headoff + (size_t)qr1 * DK + d;
            *(__half2*)&g_O16[off0] =
                __floats2half2_rn(oacc[grp][nt][0] * inv0, oacc[grp][nt][1] * inv0);
            *(__half2*)&g_O16[off1] =
                __floats2half2_rn(oacc[grp][nt][2] * inv1, oacc[grp][nt][3] * inv1);
        }
    }
}

// ---------------------------------------------------------------------------
extern "C" void kernel_launch(void* const* d_in, const int* in_sizes, int n_in,
                              void* d_out, int out_size)
{
    const float* q  = (const float*)d_in[0];
    const float* k  = (const float*)d_in[1];
    const float* v  = (const float*)d_in[2];
    const float* Wq = (const float*)d_in[3];
    const float* Wk = (const float*)d_in[4];
    const float* Wv = (const float*)d_in[5];
    const float* Wo = (const float*)d_in[6];
    float* out = (float*)d_out;

    void *pQ, *pK, *pVt;
    cudaGetSymbolAddress(&pQ, g_Q16);
    cudaGetSymbolAddress(&pK, g_K16);
    cudaGetSymbolAddress(&pVt, g_Vt16);

    cudaFuncSetAttribute(gemm_qkv, cudaFuncAttributeMaxDynamicSharedMemorySize, GSMEM);
    cudaFuncSetAttribute(gemm_o, cudaFuncAttributeMaxDynamicSharedMemorySize, GSMEM);
    cudaFuncSetAttribute(attn_mma, cudaFuncAttributeMaxDynamicSharedMemorySize, ASMEM);

    // Pre-pass
    dim3 rgrid(NBIG4 / 256, 7);
    cvt_all<<<rgrid, 256>>>(
        (const float4*)q, (const float4*)k, (const float4*)v,
        (const float4*)Wq, (const float4*)Wk, (const float4*)Wv, (const float4*)Wo);

    // Fused Q/K/V projections
    dim3 qkv_grid(DD / 128, MM / 128, 3);   // (8, 64, 3)
    gemm_qkv<<<qkv_grid, 128, GSMEM>>>();

    // Attention
    dim3 attn_grid(SS / QT, HH, BB);        // (16, 16, 4)
    attn_mma<<<attn_grid, 128, ASMEM>>>((const __half*)pQ, (const __half*)pK,
                                        (const __half*)pVt);

    // Output projection
    dim3 o_grid(DD / 128, MM / 128);        // (8, 64)
    gemm_o<<<o_grid, 128, GSMEM>>>(out);
}

// round 17
// speedup vs baseline: 1.0649x; 1.0649x over previous
#include <cuda_runtime.h>
#include <cuda_fp16.h>
#include <cstdint>
#include <cstddef>

// Problem constants
#define BB 4
#define SS 2048
#define DD 1024
#define HH 16
#define DK 64
#define MM (BB * SS)   // 8192

// fp16 operands
__device__ __half g_q16[(size_t)MM * DD];        // q * 0.125 (softmax scale folded)
__device__ __half g_k16[(size_t)MM * DD];
__device__ __half g_v16[(size_t)MM * DD];
__device__ __half g_Wq16[DD * DD];
__device__ __half g_Wk16[DD * DD];
__device__ __half g_Wv16[DD * DD];
__device__ __half g_Wo16[DD * DD];
__device__ __half g_Q16[(size_t)MM * DD];        // [B,H,S,DK]
__device__ __half g_K16[(size_t)MM * DD];        // [B,H,S,DK]
__device__ __half g_V16[(size_t)MM * DD];        // [B,H,S,DK] (trans via ldmatrix)
__device__ __half g_O16[(size_t)MM * DD];        // [B,H,S,DK]

// ---------------------------------------------------------------------------
// Helpers
// ---------------------------------------------------------------------------
__device__ __forceinline__ uint32_t smem_u32(const void* p) {
    uint32_t a;
    asm("{ .reg .u64 t; cvta.to.shared.u64 t, %1; cvt.u32.u64 %0, t; }"
        : "=r"(a) : "l"(p));
    return a;
}
__device__ __forceinline__ void cp16(uint32_t saddr, const void* gptr) {
    asm volatile("cp.async.ca.shared.global [%0], [%1], 16;"
                 :: "r"(saddr), "l"(gptr) : "memory");
}
__device__ __forceinline__ void cp_commit() {
    asm volatile("cp.async.commit_group;" ::: "memory");
}
template <int N>
__device__ __forceinline__ void cp_wait() {
    asm volatile("cp.async.wait_group %0;" :: "n"(N) : "memory");
}
// pack two fp32 -> f16x2 register (lo = first k element)
__device__ __forceinline__ uint32_t pack_h2(float lo, float hi) {
    uint32_t u;
    asm("cvt.rn.f16x2.f32 %0, %1, %2;" : "=r"(u) : "f"(hi), "f"(lo));
    return u;
}
__device__ __forceinline__ void mma_f16(float* d, const uint32_t* a, const uint32_t* b) {
    asm volatile(
        "mma.sync.aligned.m16n8k16.row.col.f32.f16.f16.f32 "
        "{%0,%1,%2,%3}, {%4,%5,%6,%7}, {%8,%9}, {%0,%1,%2,%3};"
        : "+f"(d[0]), "+f"(d[1]), "+f"(d[2]), "+f"(d[3])
        : "r"(a[0]), "r"(a[1]), "r"(a[2]), "r"(a[3]), "r"(b[0]), "r"(b[1]));
}
__device__ __forceinline__ void ldsm4(uint32_t* r, uint32_t addr) {
    asm volatile("ldmatrix.sync.aligned.m8n8.x4.shared.b16 {%0,%1,%2,%3}, [%4];"
                 : "=r"(r[0]), "=r"(r[1]), "=r"(r[2]), "=r"(r[3]) : "r"(addr));
}
__device__ __forceinline__ void ldsm4t(uint32_t* r, uint32_t addr) {
    asm volatile("ldmatrix.sync.aligned.m8n8.x4.trans.shared.b16 {%0,%1,%2,%3}, [%4];"
                 : "=r"(r[0]), "=r"(r[1]), "=r"(r[2]), "=r"(r[3]) : "r"(addr));
}

// ---------------------------------------------------------------------------
// Pre-pass: fp16 conversion of all 7 inputs. grid (8192, 7). q scaled 0.125.
// ---------------------------------------------------------------------------
#define NBIG4 ((int)((size_t)MM * DD / 4))   // 2097152
#define NW4 (DD * DD / 4)                    // 262144

__global__ __launch_bounds__(256)
void cvt_all(const float4* __restrict__ q, const float4* __restrict__ k,
             const float4* __restrict__ v, const float4* __restrict__ Wq,
             const float4* __restrict__ Wk, const float4* __restrict__ Wv,
             const float4* __restrict__ Wo)
{
    const int y = blockIdx.y;
    const int i = blockIdx.x * blockDim.x + threadIdx.x;
    const float4* src;
    __half* dst;
    int n4;
    float scale = 1.0f;
    switch (y) {
        case 0: src = q;  dst = g_q16;  n4 = NBIG4; scale = 0.125f; break;
        case 1: src = k;  dst = g_k16;  n4 = NBIG4; break;
        case 2: src = v;  dst = g_v16;  n4 = NBIG4; break;
        case 3: src = Wq; dst = g_Wq16; n4 = NW4; break;
        case 4: src = Wk; dst = g_Wk16; n4 = NW4; break;
        case 5: src = Wv; dst = g_Wv16; n4 = NW4; break;
        default: src = Wo; dst = g_Wo16; n4 = NW4; break;
    }
    if (i < n4) {
        float4 x = src[i];
        x.x *= scale; x.y *= scale; x.z *= scale; x.w *= scale;
        __half2 h0 = __floats2half2_rn(x.x, x.y);
        __half2 h1 = __floats2half2_rn(x.z, x.w);
        *(__half2*)&dst[(size_t)i * 4]     = h0;
        *(__half2*)&dst[(size_t)i * 4 + 2] = h1;
    }
}

// ---------------------------------------------------------------------------
// fp16 GEMM core: C = A @ W^T, tile 128x128, BK=64, 128 threads, 4 warps 64x64.
// 2-stage cp.async pipeline. (R14 exact.)
// ---------------------------------------------------------------------------
#define RH 72                          // halves per smem row (64 + pad 8)
#define TILEB (128 * RH * 2)           // 18432 bytes per tile
#define BUFB (2 * TILEB)               // A + B = 36864
#define GSMEM (2 * BUFB)               // 73728
#define NCHUNK (DD / 64)               // 16

template <bool GATHER>
__device__ __forceinline__ void issue_chunk(uint32_t sbuf, int it,
                                            const __half* __restrict__ A,
                                            const __half* __restrict__ W,
                                            int bm, int bn, int tid)
{
    const int k0 = it * 64;
    #pragma unroll
    for (int i = 0; i < 8; i++) {
        const int idx = i * 128 + tid;       // 0..1023 (8-half slots)
        const int r = idx >> 3;              // 0..127
        const int c8 = idx & 7;
        const int gk = k0 + c8 * 8;
        size_t aoff;
        if (GATHER) {
            const int gm = bm + r;
            const int b = gm >> 11;
            const int s = gm & (SS - 1);
            const int h = gk >> 6;
            const int dk = gk & (DK - 1);
            aoff = ((((size_t)b * HH + h) * SS + s) << 6) + dk;
        } else {
            aoff = (size_t)(bm + r) * DD + gk;
        }
        const uint32_t soff = (uint32_t)(r * RH + c8 * 8) * 2u;
        cp16(sbuf + soff, &A[aoff]);
        cp16(sbuf + TILEB + soff, &W[(size_t)(bn + r) * DD + gk]);
    }
    cp_commit();
}

template <bool GATHER>
__device__ __forceinline__ void gemm_core(const __half* __restrict__ A,
                                          const __half* __restrict__ W,
                                          float (&acc)[4][8][4],
                                          int bm, int bn, char* smem)
{
    const uint32_t sb = smem_u32(smem);
    const int tid = threadIdx.x;
    const int lane = tid & 31;
    const int wid = tid >> 5;       // 0..3
    const int wm = wid >> 1;        // 0..1 (64-row slab)
    const int wn = wid & 1;         // 0..1 (64-col slab)
    const uint32_t lrow = (uint32_t)(lane & 15);
    const uint32_t lcol = (uint32_t)(lane >> 4) * 8u;

    const uint32_t aoff = ((wm * 64 + lrow) * RH + lcol) * 2u;
    const uint32_t boff = ((wn * 64 + lrow) * RH + lcol) * 2u;

    const uint32_t sbuf[2] = { sb, sb + (uint32_t)BUFB };

    issue_chunk<GATHER>(sbuf[0], 0, A, W, bm, bn, tid);

    for (int it = 0; it < NCHUNK; ++it) {
        const int cur = it & 1;
        if (it + 1 < NCHUNK) {
            issue_chunk<GATHER>(sbuf[cur ^ 1], it + 1, A, W, bm, bn, tid);
            cp_wait<1>();
        } else {
            cp_wait<0>();
        }
        __syncthreads();

        const uint32_t aT = sbuf[cur] + aoff;
        const uint32_t bT = sbuf[cur] + TILEB + boff;
        #pragma unroll
        for (int ks = 0; ks < 4; ks++) {        // 4 k16 steps per 64-chunk
            const uint32_t koff = (uint32_t)ks * 32u;   // 16 halves
            uint32_t afr[4][4], bfr[8][2];
            #pragma unroll
            for (int mt = 0; mt < 4; mt++)
                ldsm4(afr[mt], aT + (uint32_t)(mt * 16 * RH) * 2u + koff);
            #pragma unroll
            for (int p = 0; p < 4; p++) {
                uint32_t r4[4];
                ldsm4(r4, bT + (uint32_t)(p * 16 * RH) * 2u + koff);
                bfr[2 * p][0] = r4[0]; bfr[2 * p][1] = r4[2];
                bfr[2 * p + 1][0] = r4[1]; bfr[2 * p + 1][1] = r4[3];
            }
            #pragma unroll
            for (int mt = 0; mt < 4; mt++)
                #pragma unroll
                for (int nt = 0; nt < 8; nt++)
                    mma_f16(acc[mt][nt], afr[mt], bfr[nt]);
        }
        __syncthreads();
    }
}

// Fused Q/K/V projections: grid (8, 64, 3). All outputs [B,H,S,DK], coalesced.
__global__ __launch_bounds__(128, 2)
void gemm_qkv()
{
    extern __shared__ char smem[];
    const int z = blockIdx.z;
    const __half *A, *W;
    __half* C;
    if (z == 0) { A = g_q16; W = g_Wq16; C = g_Q16; }
    else if (z == 1) { A = g_k16; W = g_Wk16; C = g_K16; }
    else { A = g_v16; W = g_Wv16; C = g_V16; }
    const int bm = blockIdx.y * 128;
    const int bn = blockIdx.x * 128;

    float acc[4][8][4];
    #pragma unroll
    for (int i = 0; i < 4; i++)
        #pragma unroll
        for (int j = 0; j < 8; j++)
            #pragma unroll
            for (int r = 0; r < 4; r++) acc[i][j][r] = 0.f;

    gemm_core<false>(A, W, acc, bm, bn, smem);

    const int lane = threadIdx.x & 31;
    const int wid = threadIdx.x >> 5;
    const int g = lane >> 2;
    const int tig = lane & 3;
    const int wm = wid >> 1;
    const int wn = wid & 1;

    #pragma unroll
    for (int mt = 0; mt < 4; mt++) {
        #pragma unroll
        for (int half = 0; half < 2; half++) {
            const int gm = bm + wm * 64 + mt * 16 + g + half * 8;
            const int b = gm >> 11;
            const int s = gm & (SS - 1);
            #pragma unroll
            for (int nt = 0; nt < 8; nt++) {
                const int gn = bn + wn * 64 + nt * 8 + 2 * tig;
                const float vx = acc[mt][nt][half * 2 + 0];
                const float vy = acc[mt][nt][half * 2 + 1];
                const int h = gn >> 6;
                const int dk = gn & (DK - 1);
                *(__half2*)&C[((((size_t)b * HH + h) * SS + s) << 6) + dk] =
                    __floats2half2_rn(vx, vy);
            }
        }
    }
}

// Output projection: gather-A from head-split O16, fp32 epilogue to out.
__global__ __launch_bounds__(128, 2)
void gemm_o(float* __restrict__ C)
{
    extern __shared__ char smem[];
    const int bm = blockIdx.y * 128;
    const int bn = blockIdx.x * 128;

    float acc[4][8][4];
    #pragma unroll
    for (int i = 0; i < 4; i++)
        #pragma unroll
        for (int j = 0; j < 8; j++)
            #pragma unroll
            for (int r = 0; r < 4; r++) acc[i][j][r] = 0.f;

    gemm_core<true>(g_O16, g_Wo16, acc, bm, bn, smem);

    const int lane = threadIdx.x & 31;
    const int wid = threadIdx.x >> 5;
    const int g = lane >> 2;
    const int tig = lane & 3;
    const int wm = wid >> 1;
    const int wn = wid & 1;

    #pragma unroll
    for (int mt = 0; mt < 4; mt++) {
        #pragma unroll
        for (int half = 0; half < 2; half++) {
            const int gm = bm + wm * 64 + mt * 16 + g + half * 8;
            #pragma unroll
            for (int nt = 0; nt < 8; nt++) {
                const int gn = bn + wn * 64 + nt * 8 + 2 * tig;
                float2 o;
                o.x = acc[mt][nt][half * 2 + 0];
                o.y = acc[mt][nt][half * 2 + 1];
                *(float2*)&C[(size_t)gm * DD + gn] = o;
            }
        }
    }
}

// ---------------------------------------------------------------------------
// fp16 causal flash attention (R14 structure). Q/K/V all [B,H,S,DK].
// CTA = 128 queries, 128 threads (each warp: 32 queries = 2 m16 groups).
// PV B-fragments via ldmatrix.trans on the row-major V tile.
// ---------------------------------------------------------------------------
#define QT 128
#define AST 72
#define ATILEB (64 * AST * 2)          // 9216 bytes per K/V tile
#define ASMEM (4 * ATILEB)             // 36864 bytes

__device__ __forceinline__ void attn_stage(uint32_t sK, uint32_t sV,
                                           const __half* __restrict__ Kh,
                                           const __half* __restrict__ Vh,
                                           size_t headoff, int kb, int tid)
{
    #pragma unroll
    for (int i = 0; i < 4; i++) {
        const int idx = i * 128 + tid;       // 0..511 (8-half slots)
        const int r = idx >> 3;              // 0..63 key row
        const int c8 = idx & 7;
        const uint32_t soff = (uint32_t)(r * AST + c8 * 8) * 2u;
        const size_t goff = headoff + (size_t)(kb * 64 + r) * DK + c8 * 8;
        cp16(sK + soff, &Kh[goff]);
        cp16(sV + soff, &Vh[goff]);
    }
    cp_commit();
}

__global__ __launch_bounds__(128, 2)
void attn_mma(const __half* __restrict__ Qh, const __half* __restrict__ Kh,
              const __half* __restrict__ Vh)
{
    extern __shared__ char smc[];
    const uint32_t sb = smem_u32(smc);
    const uint32_t sK[2] = { sb, sb + (uint32_t)ATILEB };
    const uint32_t sV[2] = { sb + 2u * ATILEB, sb + 3u * ATILEB };

    const int tid = threadIdx.x;
    const int wid = tid >> 5;
    const int lane = tid & 31;
    const int g = lane >> 2;
    const int tig = lane & 3;
    const uint32_t lrow = (uint32_t)(lane & 15);
    const uint32_t lcol = (uint32_t)(lane >> 4) * 8u;
    const int qt = gridDim.x - 1 - blockIdx.x;   // heavy tiles first
    const int h = blockIdx.y;
    const int b = blockIdx.z;
    const size_t headoff = ((size_t)(b * HH + h)) * SS * DK;
    const int nkb = 2 * qt + 2;

    // Stage 128 Q rows into the contiguous sK[0]|sK[1] region (stride AST).
    #pragma unroll
    for (int i = 0; i < 8; i++) {
        const int idx = i * 128 + tid;       // 0..1023
        const int r = idx >> 3;
        const int c8 = idx & 7;
        cp16(sK[0] + (uint32_t)(r * AST + c8 * 8) * 2u,
             &Qh[headoff + (size_t)(qt * QT + r) * DK + c8 * 8]);
    }
    cp_commit();
    cp_wait<0>();
    __syncthreads();

    // Q fragments: 2 groups x 4 k16 steps x 4 regs.
    uint32_t qf[2][4][4];
    #pragma unroll
    for (int grp = 0; grp < 2; grp++) {
        const uint32_t qbase = sK[0]
            + ((wid * 32 + grp * 16 + lrow) * AST + lcol) * 2u;
        #pragma unroll
        for (int ks = 0; ks < 4; ks++)
            ldsm4(qf[grp][ks], qbase + (uint32_t)ks * 32u);
    }
    __syncthreads();

    attn_stage(sK[0], sV[0], Kh, Vh, headoff, 0, tid);

    const uint32_t foff = (lrow * AST + lcol) * 2u;

    float oacc[2][8][4];
    #pragma unroll
    for (int grp = 0; grp < 2; grp++)
        #pragma unroll
        for (int nt = 0; nt < 8; nt++)
            #pragma unroll
            for (int r = 0; r < 4; r++) oacc[grp][nt][r] = 0.f;
    float m[2][2] = { {-1e30f, -1e30f}, {-1e30f, -1e30f} };
    float l[2][2] = { {0.f, 0.f}, {0.f, 0.f} };

    for (int kb = 0; kb < nkb; kb++) {
        const int cur = kb & 1;
        if (kb + 1 < nkb) {
            attn_stage(sK[cur ^ 1], sV[cur ^ 1], Kh, Vh, headoff, kb + 1, tid);
            cp_wait<1>();
        } else {
            cp_wait<0>();
        }
        __syncthreads();

        // ---- S = Q K^T (k16 MMA, shared K fragments across groups) ----
        float sacc[2][8][4];
        #pragma unroll
        for (int grp = 0; grp < 2; grp++)
            #pragma unroll
            for (int nt = 0; nt < 8; nt++)
                #pragma unroll
                for (int r = 0; r < 4; r++) sacc[grp][nt][r] = 0.f;

        const uint32_t kT = sK[cur] + foff;
        #pragma unroll
        for (int ks = 0; ks < 4; ks++) {
            uint32_t bfr[8][2];
            #pragma unroll
            for (int p = 0; p < 4; p++) {
                uint32_t r4[4];
                ldsm4(r4, kT + (uint32_t)(p * 16 * AST) * 2u + (uint32_t)ks * 32u);
                bfr[2 * p][0] = r4[0]; bfr[2 * p][1] = r4[2];
                bfr[2 * p + 1][0] = r4[1]; bfr[2 * p + 1][1] = r4[3];
            }
            #pragma unroll
            for (int grp = 0; grp < 2; grp++)
                #pragma unroll
                for (int nt = 0; nt < 8; nt++)
                    mma_f16(sacc[grp][nt], qf[grp][ks], bfr[nt]);
        }

        // ---- causal mask (last two k-blocks only) ----
        const int rel = (kb - 2 * qt) * 64;
        if (rel >= 0) {
            #pragma unroll
            for (int grp = 0; grp < 2; grp++) {
                const int ql0 = wid * 32 + grp * 16 + g;
                const int ql1 = ql0 + 8;
                #pragma unroll
                for (int nt = 0; nt < 8; nt++) {
                    const int kc = rel + nt * 8 + 2 * tig;
                    if (kc > ql0)     sacc[grp][nt][0] = -1e30f;
                    if (kc + 1 > ql0) sacc[grp][nt][1] = -1e30f;
                    if (kc > ql1)     sacc[grp][nt][2] = -1e30f;
                    if (kc + 1 > ql1) sacc[grp][nt][3] = -1e30f;
                }
            }
        }

        // ---- online softmax bookkeeping per group ----
        float nm[2][2];
        #pragma unroll
        for (int grp = 0; grp < 2; grp++) {
            float tmax0 = -1e30f, tmax1 = -1e30f;
            #pragma unroll
            for (int nt = 0; nt < 8; nt++) {
                tmax0 = fmaxf(tmax0, fmaxf(sacc[grp][nt][0], sacc[grp][nt][1]));
                tmax1 = fmaxf(tmax1, fmaxf(sacc[grp][nt][2], sacc[grp][nt][3]));
            }
            tmax0 = fmaxf(tmax0, __shfl_xor_sync(0xffffffffu, tmax0, 1));
            tmax0 = fmaxf(tmax0, __shfl_xor_sync(0xffffffffu, tmax0, 2));
            tmax1 = fmaxf(tmax1, __shfl_xor_sync(0xffffffffu, tmax1, 1));
            tmax1 = fmaxf(tmax1, __shfl_xor_sync(0xffffffffu, tmax1, 2));
            const float nm0 = fmaxf(m[grp][0], tmax0);
            const float nm1 = fmaxf(m[grp][1], tmax1);
            const float corr0 = __expf(m[grp][0] - nm0);
            const float corr1 = __expf(m[grp][1] - nm1);
            l[grp][0] *= corr0;
            l[grp][1] *= corr1;
            #pragma unroll
            for (int nt = 0; nt < 8; nt++) {
                oacc[grp][nt][0] *= corr0; oacc[grp][nt][1] *= corr0;
                oacc[grp][nt][2] *= corr1; oacc[grp][nt][3] *= corr1;
            }
            m[grp][0] = nm0; m[grp][1] = nm1;
            nm[grp][0] = nm0; nm[grp][1] = nm1;
        }

        // ---- PV: exp in C layout == A layout; B-fragments via ldsm.trans ----
        const uint32_t vT = sV[cur] + foff;
        #pragma unroll
        for (int ks2 = 0; ks2 < 4; ks2++) {     // 16 keys per step
            uint32_t bfr[8][2];
            #pragma unroll
            for (int p = 0; p < 4; p++) {       // 16 dk columns per trans-load
                uint32_t r4[4];
                ldsm4t(r4, vT + (uint32_t)(ks2 * 16 * AST) * 2u + (uint32_t)(p * 16) * 2u);
                bfr[2 * p][0] = r4[0]; bfr[2 * p][1] = r4[1];
                bfr[2 * p + 1][0] = r4[2]; bfr[2 * p + 1][1] = r4[3];
            }
            #pragma unroll
            for (int grp = 0; grp < 2; grp++) {
                const int nt0 = 2 * ks2, nt1 = 2 * ks2 + 1;
                const float p00 = __expf(sacc[grp][nt0][0] - nm[grp][0]);
                const float p01 = __expf(sacc[grp][nt0][1] - nm[grp][0]);
                const float p02 = __expf(sacc[grp][nt0][2] - nm[grp][1]);
                const float p03 = __expf(sacc[grp][nt0][3] - nm[grp][1]);
                const float p10 = __expf(sacc[grp][nt1][0] - nm[grp][0]);
                const float p11 = __expf(sacc[grp][nt1][1] - nm[grp][0]);
                const float p12 = __expf(sacc[grp][nt1][2] - nm[grp][1]);
                const float p13 = __expf(sacc[grp][nt1][3] - nm[grp][1]);
                l[grp][0] += (p00 + p01) + (p10 + p11);
                l[grp][1] += (p02 + p03) + (p12 + p13);
                uint32_t af[4];
                af[0] = pack_h2(p00, p01);
                af[1] = pack_h2(p02, p03);
                af[2] = pack_h2(p10, p11);
                af[3] = pack_h2(p12, p13);
                #pragma unroll
                for (int nt = 0; nt < 8; nt++)
                    mma_f16(oacc[grp][nt], af, bfr[nt]);
            }
        }
        __syncthreads();
    }

    // Epilogue: O as fp16 head-split (consumed by gemm_o).
    #pragma unroll
    for (int grp = 0; grp < 2; grp++) {
        float la = l[grp][0], lb = l[grp][1];
        la += __shfl_xor_sync(0xffffffffu, la, 1);
        la += __shfl_xor_sync(0xffffffffu, la, 2);
        lb += __shfl_xor_sync(0xffffffffu, lb, 1);
        lb += __shfl_xor_sync(0xffffffffu, lb, 2);
        const float inv0 = 1.f / la;
        const float inv1 = 1.f / lb;
        const int qr0 = qt * QT + wid * 32 + grp * 16 + g;
        const int qr1 = qr0 + 8;
        #pragma unroll
        for (int nt = 0; nt < 8; nt++) {
            const int d = nt * 8 + 2 * tig;
            const size_t off0 = headoff + (size_t)qr0 * DK + d;
            const size_t off1 = headoff + (size_t)qr1 * DK + d;
            *(__half2*)&g_O16[off0] =
                __floats2half2_rn(oacc[grp][nt][0] * inv0, oacc[grp][nt][1] * inv0);
            *(__half2*)&g_O16[off1] =
                __floats2half2_rn(oacc[grp][nt][2] * inv1, oacc[grp][nt][3] * inv1);
        }
    }
}

// ---------------------------------------------------------------------------
extern "C" void kernel_launch(void* const* d_in, const int* in_sizes, int n_in,
                              void* d_out, int out_size)
{
    const float* q  = (const float*)d_in[0];
    const float* k  = (const float*)d_in[1];
    const float* v  = (const float*)d_in[2];
    const float* Wq = (const float*)d_in[3];
    const float* Wk = (const float*)d_in[4];
    const float* Wv = (const float*)d_in[5];
    const float* Wo = (const float*)d_in[6];
    float* out = (float*)d_out;

    void *pQ, *pK, *pV;
    cudaGetSymbolAddress(&pQ, g_Q16);
    cudaGetSymbolAddress(&pK, g_K16);
    cudaGetSymbolAddress(&pV, g_V16);

    cudaFuncSetAttribute(gemm_qkv, cudaFuncAttributeMaxDynamicSharedMemorySize, GSMEM);
    cudaFuncSetAttribute(gemm_o, cudaFuncAttributeMaxDynamicSharedMemorySize, GSMEM);
    cudaFuncSetAttribute(attn_mma, cudaFuncAttributeMaxDynamicSharedMemorySize, ASMEM);

    // Pre-pass
    dim3 rgrid(NBIG4 / 256, 7);
    cvt_all<<<rgrid, 256>>>(
        (const float4*)q, (const float4*)k, (const float4*)v,
        (const float4*)Wq, (const float4*)Wk, (const float4*)Wv, (const float4*)Wo);

    // Fused Q/K/V projections
    dim3 qkv_grid(DD / 128, MM / 128, 3);   // (8, 64, 3)
    gemm_qkv<<<qkv_grid, 128, GSMEM>>>();

    // Attention
    dim3 attn_grid(SS / QT, HH, BB);        // (16, 16, 4)
    attn_mma<<<attn_grid, 128, ASMEM>>>((const __half*)pQ, (const __half*)pK,
                                        (const __half*)pV);

    // Output projection
    dim3 o_grid(DD / 128, MM / 128);        // (8, 64)
    gemm_o<<<o_grid, 128, GSMEM>>>(out);
}